// round 15
// baseline (speedup 1.0000x reference)
#include <cuda_runtime.h>
#include <cuda_bf16.h>
#include <stdint.h>

// Problem constants
#define KCODES 1024
#define DDIM   256
#define NROWS  65536
#define DECAYF 0.99f
#define ONE_MINUS_DECAY 0.01f
#define BETAF  0.25f
#define EPSF   1e-5f
#define GAPF   2e-3f      // flag threshold: covers bf16-split dot error w/ margin

// Scratch (__device__ globals; no allocations allowed)
__device__ __align__(16) __nv_bfloat16 g_zh[NROWS * DDIM];
__device__ __align__(16) __nv_bfloat16 g_zl[NROWS * DDIM];
__device__ __align__(16) __nv_bfloat16 g_eh[KCODES * DDIM];
__device__ __align__(16) __nv_bfloat16 g_el[KCODES * DDIM];
__device__ float  g_esq[KCODES];
__device__ float  g_zsq[NROWS];
__device__ int    g_codes[NROWS];
__device__ int    g_flag_list[NROWS];
__device__ int    g_flag_cnt;
__device__ int    g_hist[KCODES];
__device__ int    g_off[KCODES];
__device__ int    g_cursor[KCODES];
__device__ int    g_row_of[NROWS];
__device__ float  g_embed_sum[KCODES * DDIM];
__device__ double g_loss;
__device__ float  g_nsum;

// ---------------------------------------------------------------------------
// k_init_small: zero hist + counters. One block.
// ---------------------------------------------------------------------------
__global__ __launch_bounds__(1024) void k_init_small() {
    int t = threadIdx.x;
    g_hist[t] = 0;
    if (t == 0) { g_loss = 0.0; g_nsum = 0.0f; g_flag_cnt = 0; }
}

// ---------------------------------------------------------------------------
// k_split_all: fused split for z AND emb. fp32 -> bf16 hi + lo (residual),
// fused fp64 row sum-of-sq. Half-warp per row; block = 16 rows.
// Blocks [0, N/16) -> z ; blocks [N/16, N/16+K/16) -> emb.
// ---------------------------------------------------------------------------
__global__ __launch_bounds__(256) void k_split_all(const float* __restrict__ z,
                                                   const float* __restrict__ e) {
    const int tid  = threadIdx.x;
    const int warp = tid >> 5;
    const int lane = tid & 31;
    const int half = lane & 15;

    const float* src;
    __nv_bfloat16 *h, *l;
    float* sq;
    int rbase;
    if (blockIdx.x < NROWS / 16) {
        src = z; h = g_zh; l = g_zl; sq = g_zsq;
        rbase = blockIdx.x * 16;
    } else {
        src = e; h = g_eh; l = g_el; sq = g_esq;
        rbase = (blockIdx.x - NROWS / 16) * 16;
    }
    const int row = rbase + warp * 2 + (lane >> 4);

    const float4* srow = (const float4*)(src + (size_t)row * DDIM);
    float4 v[4];
#pragma unroll
    for (int j = 0; j < 4; j++) v[j] = srow[half * 4 + j];

    double s = 0.0;
    uint32_t hw[8], lw[8];
#pragma unroll
    for (int j = 0; j < 4; j++) {
        float4 w = v[j];
        __nv_bfloat16 h0 = __float2bfloat16_rn(w.x);
        __nv_bfloat16 h1 = __float2bfloat16_rn(w.y);
        __nv_bfloat16 h2 = __float2bfloat16_rn(w.z);
        __nv_bfloat16 h3 = __float2bfloat16_rn(w.w);
        __nv_bfloat162 hp0; hp0.x = h0; hp0.y = h1;
        __nv_bfloat162 hp1; hp1.x = h2; hp1.y = h3;
        hw[j * 2 + 0] = *(uint32_t*)&hp0;
        hw[j * 2 + 1] = *(uint32_t*)&hp1;
        __nv_bfloat162 lp0, lp1;
        lp0.x = __float2bfloat16_rn(w.x - __bfloat162float(h0));
        lp0.y = __float2bfloat16_rn(w.y - __bfloat162float(h1));
        lp1.x = __float2bfloat16_rn(w.z - __bfloat162float(h2));
        lp1.y = __float2bfloat16_rn(w.w - __bfloat162float(h3));
        lw[j * 2 + 0] = *(uint32_t*)&lp0;
        lw[j * 2 + 1] = *(uint32_t*)&lp1;
        s += (double)w.x * w.x + (double)w.y * w.y
           + (double)w.z * w.z + (double)w.w * w.w;
    }
    uint4* hp = (uint4*)(h + (size_t)row * DDIM + half * 16);
    uint4* lp = (uint4*)(l + (size_t)row * DDIM + half * 16);
    hp[0] = make_uint4(hw[0], hw[1], hw[2], hw[3]);
    hp[1] = make_uint4(hw[4], hw[5], hw[6], hw[7]);
    lp[0] = make_uint4(lw[0], lw[1], lw[2], lw[3]);
    lp[1] = make_uint4(lw[4], lw[5], lw[6], lw[7]);

#pragma unroll
    for (int off = 8; off > 0; off >>= 1)
        s += __shfl_xor_sync(0xffffffffu, s, off);
    if (half == 0) sq[row] = (float)s;
}

// ---------------------------------------------------------------------------
// async-copy / mma helpers
// ---------------------------------------------------------------------------
__device__ __forceinline__ void cp_async16(uint32_t dst, const void* src) {
    asm volatile("cp.async.cg.shared.global [%0], [%1], 16;" :: "r"(dst), "l"(src));
}
__device__ __forceinline__ void cp_commit() {
    asm volatile("cp.async.commit_group;");
}
template <int N> __device__ __forceinline__ void cp_wait() {
    asm volatile("cp.async.wait_group %0;" :: "n"(N));
}
__device__ __forceinline__ void ldsm_x4(uint32_t& r0, uint32_t& r1, uint32_t& r2, uint32_t& r3,
                                        uint32_t addr) {
    asm volatile("ldmatrix.sync.aligned.m8n8.x4.shared.b16 {%0,%1,%2,%3}, [%4];"
                 : "=r"(r0), "=r"(r1), "=r"(r2), "=r"(r3) : "r"(addr));
}
__device__ __forceinline__ void mma_bf16(float* cfr, uint32_t a0, uint32_t a1, uint32_t a2,
                                         uint32_t a3, uint32_t b0, uint32_t b1) {
    asm volatile("mma.sync.aligned.m16n8k16.row.col.f32.bf16.bf16.f32 "
                 "{%0,%1,%2,%3}, {%4,%5,%6,%7}, {%8,%9}, {%0,%1,%2,%3};"
                 : "+f"(cfr[0]), "+f"(cfr[1]), "+f"(cfr[2]), "+f"(cfr[3])
                 : "r"(a0), "r"(a1), "r"(a2), "r"(a3), "r"(b0), "r"(b1));
}
__device__ __forceinline__ void upd(float& b, float& s, int& i, float v, int col) {
    if (v < b) { s = b; b = v; i = col; }
    else if (v < s) { s = v; }
}
__device__ __forceinline__ void merge2(float& b, float& s, int& i,
                                       float ob, float os, int oi) {
    float ns = fminf(s, os);
    if (ob < b || (ob == b && oi < i)) { ns = fminf(ns, b); b = ob; i = oi; }
    else { ns = fminf(ns, ob); }
    s = ns;
}

// ---------------------------------------------------------------------------
// Kernel 1: 3-term bf16-split GEMM via mma.sync, cp.async double-buffered,
// fused quantized-distance argmin, flag compaction, loss sum, histogram.
// (identical to the R12 passing version + one atomicAdd for the histogram)
// ---------------------------------------------------------------------------
#define PITCH_B   80
#define TILE_ST   (128 * PITCH_B)
#define STAGE_ST  (4 * TILE_ST)
#define SMEM_TILES (2 * STAGE_ST)
#define SMEM_K1   (SMEM_TILES + 512 + 3 * 1024)

__global__ __launch_bounds__(256, 2) void k1_mma(int* __restrict__ codes_i,
                                                 float* __restrict__ codes_f) {
    extern __shared__ char smem[];
    float* sEsq = (float*)(smem + SMEM_TILES);
    float* sFb  = (float*)(smem + SMEM_TILES + 512);
    float* sFs  = (float*)(smem + SMEM_TILES + 512 + 1024);
    int*   sFi  = (int*)  (smem + SMEM_TILES + 512 + 2048);

    const int tid  = threadIdx.x;
    const int lane = tid & 31;
    const int warp = tid >> 5;
    const int wm   = warp & 3;
    const int wn   = warp >> 2;
    const int row0 = blockIdx.x * 128;
    const uint32_t sbase = (uint32_t)__cvta_generic_to_shared(smem);

    const int rbase = wm * 32 + (lane >> 2);
    float zs[4];
#pragma unroll
    for (int r = 0; r < 4; r++) zs[r] = g_zsq[row0 + rbase + r * 8];

    float best[4], secv[4];
    int   bidx[4];
#pragma unroll
    for (int r = 0; r < 4; r++) { best[r] = 3.0e38f; secv[r] = 3.0e38f; bidx[r] = 0x7fffffff; }

    auto issue = [&](int kc, int st, int n0) {
        const int k0 = kc * 32;
#pragma unroll
        for (int it = 0; it < 8; it++) {
            int tile = it >> 1;
            int rr   = ((tid >> 2) + it * 64) & 127;
            int sub  = tid & 3;
            const __nv_bfloat16* gp;
            if      (tile == 0) gp = g_zh + (size_t)(row0 + rr) * DDIM;
            else if (tile == 1) gp = g_zl + (size_t)(row0 + rr) * DDIM;
            else if (tile == 2) gp = g_eh + (size_t)(n0 + rr) * DDIM;
            else                gp = g_el + (size_t)(n0 + rr) * DDIM;
            uint32_t dst = sbase + st * STAGE_ST + tile * TILE_ST + rr * PITCH_B + sub * 16;
            cp_async16(dst, gp + k0 + sub * 8);
        }
        cp_commit();
    };

    for (int n0 = 0; n0 < KCODES; n0 += 128) {
        __syncthreads();
        if (tid < 128) sEsq[tid] = g_esq[n0 + tid];

        float acc[2][8][4];
#pragma unroll
        for (int mt = 0; mt < 2; mt++)
#pragma unroll
            for (int nt = 0; nt < 8; nt++)
#pragma unroll
                for (int q = 0; q < 4; q++) acc[mt][nt][q] = 0.0f;

        issue(0, 0, n0);

        for (int kc = 0; kc < 8; kc++) {
            if (kc < 7) issue(kc + 1, (kc + 1) & 1, n0);
            if (kc < 7) cp_wait<1>(); else cp_wait<0>();
            __syncthreads();

            const int st = kc & 1;
            const uint32_t bAh = sbase + st * STAGE_ST;
            const uint32_t bAl = bAh + TILE_ST;
            const uint32_t bBh = bAh + 2 * TILE_ST;
            const uint32_t bBl = bAh + 3 * TILE_ST;

#pragma unroll
            for (int ks = 0; ks < 2; ks++) {
                const uint32_t koff = ks * 32;
                uint32_t Ah[2][4], Al[2][4];
#pragma unroll
                for (int mt = 0; mt < 2; mt++) {
                    uint32_t off = (uint32_t)(wm * 32 + mt * 16 + (lane & 15)) * PITCH_B
                                 + koff + ((lane >> 4) & 1) * 16;
                    ldsm_x4(Ah[mt][0], Ah[mt][1], Ah[mt][2], Ah[mt][3], bAh + off);
                    ldsm_x4(Al[mt][0], Al[mt][1], Al[mt][2], Al[mt][3], bAl + off);
                }
                const int g  = lane >> 3;
                const int rb = lane & 7;
#pragma unroll
                for (int ntp = 0; ntp < 4; ntp++) {
                    uint32_t nrow = (uint32_t)(wn * 64 + (ntp * 2 + (g >> 1)) * 8 + rb);
                    uint32_t off  = nrow * PITCH_B + koff + (g & 1) * 16;
                    uint32_t Bh0, Bh1, Bh2, Bh3, Bl0, Bl1, Bl2, Bl3;
                    ldsm_x4(Bh0, Bh1, Bh2, Bh3, bBh + off);
                    ldsm_x4(Bl0, Bl1, Bl2, Bl3, bBl + off);
                    const int nt0 = ntp * 2, nt1 = nt0 + 1;
#pragma unroll
                    for (int mt = 0; mt < 2; mt++) {
                        mma_bf16(acc[mt][nt0], Ah[mt][0], Ah[mt][1], Ah[mt][2], Ah[mt][3], Bh0, Bh1);
                        mma_bf16(acc[mt][nt0], Al[mt][0], Al[mt][1], Al[mt][2], Al[mt][3], Bh0, Bh1);
                        mma_bf16(acc[mt][nt0], Ah[mt][0], Ah[mt][1], Ah[mt][2], Ah[mt][3], Bl0, Bl1);
                        mma_bf16(acc[mt][nt1], Ah[mt][0], Ah[mt][1], Ah[mt][2], Ah[mt][3], Bh2, Bh3);
                        mma_bf16(acc[mt][nt1], Al[mt][0], Al[mt][1], Al[mt][2], Al[mt][3], Bh2, Bh3);
                        mma_bf16(acc[mt][nt1], Ah[mt][0], Ah[mt][1], Ah[mt][2], Ah[mt][3], Bl2, Bl3);
                    }
                }
            }
            __syncthreads();
        }

        const int qc = lane & 3;
#pragma unroll
        for (int nt = 0; nt < 8; nt++) {
#pragma unroll
            for (int cp = 0; cp < 2; cp++) {
                int cl  = wn * 64 + nt * 8 + qc * 2 + cp;
                float esq = sEsq[cl];
                int col = n0 + cl;
                float v;
                v = __fadd_rn(__fadd_rn(zs[0], -2.0f * acc[0][nt][cp]),     esq);
                upd(best[0], secv[0], bidx[0], v, col);
                v = __fadd_rn(__fadd_rn(zs[1], -2.0f * acc[0][nt][2 + cp]), esq);
                upd(best[1], secv[1], bidx[1], v, col);
                v = __fadd_rn(__fadd_rn(zs[2], -2.0f * acc[1][nt][cp]),     esq);
                upd(best[2], secv[2], bidx[2], v, col);
                v = __fadd_rn(__fadd_rn(zs[3], -2.0f * acc[1][nt][2 + cp]), esq);
                upd(best[3], secv[3], bidx[3], v, col);
            }
        }
    }

#pragma unroll
    for (int off = 1; off <= 2; off <<= 1) {
#pragma unroll
        for (int r = 0; r < 4; r++) {
            float ob = __shfl_xor_sync(0xffffffffu, best[r], off);
            float os = __shfl_xor_sync(0xffffffffu, secv[r], off);
            int   oi = __shfl_xor_sync(0xffffffffu, bidx[r], off);
            merge2(best[r], secv[r], bidx[r], ob, os, oi);
        }
    }
    if ((lane & 3) == 0) {
#pragma unroll
        for (int r = 0; r < 4; r++) {
            int rl = wm * 32 + (lane >> 2) + r * 8;
            sFb[rl * 2 + wn] = best[r];
            sFs[rl * 2 + wn] = secv[r];
            sFi[rl * 2 + wn] = bidx[r];
        }
    }
    __syncthreads();
    float* sLoss = sFs;
    if (tid < 128) {
        float b = sFb[tid * 2], s = sFs[tid * 2];
        int   i = sFi[tid * 2];
        merge2(b, s, i, sFb[tid * 2 + 1], sFs[tid * 2 + 1], sFi[tid * 2 + 1]);
        int row = row0 + tid;
        codes_i[row] = i;
        codes_f[row] = (float)i;
        atomicAdd(&g_hist[i], 1);            // fused histogram
        if (s - b <= GAPF) {
            int p = atomicAdd(&g_flag_cnt, 1);
            g_flag_list[p] = row;
        }
        sFb[tid] = b;
    }
    __syncthreads();
    if (tid < 64) sLoss[tid] = sFb[tid] + sFb[tid + 64];
    __syncthreads();
    if (tid < 32) {
        float s = sLoss[tid] + sLoss[tid + 32];
#pragma unroll
        for (int off = 16; off > 0; off >>= 1)
            s += __shfl_down_sync(0xffffffffu, s, off);
        if (tid == 0) atomicAdd(&g_loss, (double)s);
    }
}

// ---------------------------------------------------------------------------
// k1_refine: exact fp64-dot recompute for flagged rows + histogram fixup.
// ---------------------------------------------------------------------------
__global__ __launch_bounds__(256) void k1_refine(const float* __restrict__ z,
                                                 const float* __restrict__ emb,
                                                 int* __restrict__ codes_i,
                                                 float* __restrict__ codes_f) {
    __shared__ float zrow[DDIM];
    __shared__ float sv[256];
    __shared__ int   si[256];
    int t = threadIdx.x;
    int cnt = g_flag_cnt;
    for (int fi = blockIdx.x; fi < cnt; fi += gridDim.x) {
        int row = g_flag_list[fi];
        zrow[t] = z[(size_t)row * DDIM + t];
        __syncthreads();

        float zsq = g_zsq[row];
        float bv = 3.0e38f;
        int   bi = 0x7fffffff;
        for (int c = t; c < KCODES; c += 256) {
            const float4* e4 = (const float4*)(emb + (size_t)c * DDIM);
            const float4* z4 = (const float4*)zrow;
            double dot = 0.0;
#pragma unroll 8
            for (int q = 0; q < DDIM / 4; q++) {
                float4 ev = e4[q];
                float4 zv = z4[q];
                dot += (double)zv.x * ev.x + (double)zv.y * ev.y
                     + (double)zv.z * ev.z + (double)zv.w * ev.w;
            }
            float m = (float)(2.0 * dot);
            float u = __fadd_rn(zsq, -m);
            float v = __fadd_rn(u, g_esq[c]);
            if (v < bv) { bv = v; bi = c; }
        }
        sv[t] = bv; si[t] = bi;
        __syncthreads();
        for (int s = 128; s > 0; s >>= 1) {
            if (t < s) {
                float v = sv[t + s]; int id = si[t + s];
                if (v < sv[t] || (v == sv[t] && id < si[t])) { sv[t] = v; si[t] = id; }
            }
            __syncthreads();
        }
        if (t == 0) {
            int oldc = codes_i[row];
            int newc = si[0];
            if (newc != oldc) {              // histogram fixup
                atomicAdd(&g_hist[oldc], -1);
                atomicAdd(&g_hist[newc], 1);
                codes_i[row] = newc;
                codes_f[row] = (float)newc;
            }
        }
        __syncthreads();
    }
}

// ---------------------------------------------------------------------------
// kP: prefix-scan of hist + new_cluster_size + nsum + vq_loss. One block.
// ---------------------------------------------------------------------------
__global__ __launch_bounds__(KCODES) void kP(const float* __restrict__ cs_in,
                                             float* __restrict__ cs_out,
                                             float* __restrict__ loss_out,
                                             float inv_nd) {
    __shared__ int sc[KCODES], sc2[KCODES];
    __shared__ float red[KCODES];
    int t = threadIdx.x;
    int hcnt = g_hist[t];
    sc[t] = hcnt;
    __syncthreads();
    int* src = sc;
    int* dst = sc2;
    for (int off = 1; off < KCODES; off <<= 1) {
        int v = src[t];
        if (t >= off) v += src[t - off];
        dst[t] = v;
        __syncthreads();
        int* tmp = src; src = dst; dst = tmp;
    }
    int excl = src[t] - hcnt;
    g_off[t] = excl;
    g_cursor[t] = excl;
    float ncs = cs_in[t] * DECAYF + (float)hcnt * ONE_MINUS_DECAY;
    cs_out[t] = ncs;
    red[t] = ncs;
    __syncthreads();
    for (int s = KCODES / 2; s > 0; s >>= 1) {
        if (t < s) red[t] += red[t + s];
        __syncthreads();
    }
    if (t == 0) {
        g_nsum = red[0];
        loss_out[0] = BETAF * (float)(g_loss * (double)inv_nd);
    }
}

// ---------------------------------------------------------------------------
// kS: scatter row ids by code (cursor atomics). grid 256 x 256.
// ---------------------------------------------------------------------------
__global__ __launch_bounds__(256) void kS() {
    int row = blockIdx.x * 256 + threadIdx.x;
    int c = g_codes[row];
    int p = atomicAdd(&g_cursor[c], 1);
    g_row_of[p] = row;
}

// ---------------------------------------------------------------------------
// kSum: segmented sum -> embed_sum AND zq write (fused gather).
// One block per code; thread t owns dim t. Holds emb[c][t] in a register,
// streams it to every row of its segment (coalesced 1KB row writes).
// ---------------------------------------------------------------------------
__global__ __launch_bounds__(DDIM) void kSum(const float* __restrict__ z,
                                             const float* __restrict__ emb,
                                             float* __restrict__ zq_out) {
    int c = blockIdx.x;
    int t = threadIdx.x;
    int off = g_off[c];
    int cnt = g_hist[c];
    float ev = emb[(size_t)c * DDIM + t];
    float acc = 0.0f;
    int i = 0;
    for (; i + 4 <= cnt; i += 4) {
        int r0 = g_row_of[off + i];
        int r1 = g_row_of[off + i + 1];
        int r2 = g_row_of[off + i + 2];
        int r3 = g_row_of[off + i + 3];
        acc += z[(size_t)r0 * DDIM + t] + z[(size_t)r1 * DDIM + t]
             + z[(size_t)r2 * DDIM + t] + z[(size_t)r3 * DDIM + t];
        zq_out[(size_t)r0 * DDIM + t] = ev;
        zq_out[(size_t)r1 * DDIM + t] = ev;
        zq_out[(size_t)r2 * DDIM + t] = ev;
        zq_out[(size_t)r3 * DDIM + t] = ev;
    }
    for (; i < cnt; i++) {
        int r = g_row_of[off + i];
        acc += z[(size_t)r * DDIM + t];
        zq_out[(size_t)r * DDIM + t] = ev;
    }
    g_embed_sum[(size_t)c * DDIM + t] = acc;
}

// ---------------------------------------------------------------------------
// k4: new_embed_avg + smoothed normalize -> new_embedding
// ---------------------------------------------------------------------------
__global__ __launch_bounds__(DDIM) void k4_embed(const float* __restrict__ avg_in,
                                                 const float* __restrict__ cs_out,
                                                 float* __restrict__ avg_out,
                                                 float* __restrict__ emb_out) {
    int k = blockIdx.x;
    int t = threadIdx.x;
    size_t idx = (size_t)k * DDIM + t;
    float na = avg_in[idx] * DECAYF + g_embed_sum[idx] * ONE_MINUS_DECAY;
    avg_out[idx] = na;
    float n = g_nsum;
    float css = (cs_out[k] + EPSF) / (n + (float)KCODES * EPSF) * n;
    emb_out[idx] = na / css;
}

// ---------------------------------------------------------------------------
extern "C" void kernel_launch(void* const* d_in, const int* in_sizes, int n_in,
                              void* d_out, int out_size) {
    const float* z_e  = (const float*)d_in[0];  // [N, D]
    const float* emb  = (const float*)d_in[1];  // [K, D]
    const float* cs   = (const float*)d_in[2];  // [K]
    const float* eavg = (const float*)d_in[3];  // [K, D]

    const int n_ze = in_sizes[0];               // N*D
    const int KD   = in_sizes[1];               // K*D
    const int Kk   = in_sizes[2];               // K
    const int D    = KD / Kk;
    const int N    = n_ze / D;

    float* out = (float*)d_out;
    // Tuple order: z_q_st, vq_loss, codes, new_embedding, new_cluster_size, new_embed_avg
    float* o_zq    = out;
    float* o_loss  = out + (size_t)n_ze;
    float* o_codes = o_loss + 1;
    float* o_emb   = o_codes + N;
    float* o_cs    = o_emb + KD;
    float* o_avg   = o_cs + Kk;

    int* codes_dev;
    cudaGetSymbolAddress((void**)&codes_dev, g_codes);

    cudaFuncSetAttribute(k1_mma, cudaFuncAttributeMaxDynamicSharedMemorySize, SMEM_K1);

    k_init_small<<<1, 1024>>>();
    k_split_all<<<N / 16 + Kk / 16, 256>>>(z_e, emb);
    k1_mma<<<N / 128, 256, SMEM_K1>>>(codes_dev, o_codes);
    k1_refine<<<256, 256>>>(z_e, emb, codes_dev, o_codes);
    kP<<<1, Kk>>>(cs, o_cs, o_loss, 1.0f / (float)n_ze);
    kS<<<N / 256, 256>>>();
    kSum<<<Kk, D>>>(z_e, emb, o_zq);
    k4_embed<<<Kk, D>>>(eavg, o_cs, o_avg, o_emb);
}

// round 16
// speedup vs baseline: 2.0978x; 2.0978x over previous
#include <cuda_runtime.h>
#include <cuda_bf16.h>
#include <stdint.h>

// Problem constants
#define KCODES 1024
#define DDIM   256
#define NROWS  65536
#define DECAYF 0.99f
#define ONE_MINUS_DECAY 0.01f
#define BETAF  0.25f
#define EPSF   1e-5f
#define GAPF   1e-3f      // flag threshold: 10x margin over est. max bf16-split error (~1e-4)

// Scratch (__device__ globals; no allocations allowed)
__device__ __align__(16) __nv_bfloat16 g_zh[NROWS * DDIM];
__device__ __align__(16) __nv_bfloat16 g_zl[NROWS * DDIM];
__device__ __align__(16) __nv_bfloat16 g_eh[KCODES * DDIM];
__device__ __align__(16) __nv_bfloat16 g_el[KCODES * DDIM];
__device__ float  g_esq[KCODES];
__device__ float  g_zsq[NROWS];
__device__ int    g_codes[NROWS];
__device__ int    g_flag_list[NROWS];
__device__ int    g_flag_cnt;
__device__ int    g_hist[KCODES];
__device__ int    g_off[KCODES];
__device__ int    g_cursor[KCODES];
__device__ int    g_row_of[NROWS];
__device__ float  g_embed_sum[KCODES * DDIM];
__device__ double g_loss;
__device__ float  g_nsum;

// ---------------------------------------------------------------------------
// k_init_small: zero hist + counters. One block.
// ---------------------------------------------------------------------------
__global__ __launch_bounds__(1024) void k_init_small() {
    int t = threadIdx.x;
    g_hist[t] = 0;
    if (t == 0) { g_loss = 0.0; g_nsum = 0.0f; g_flag_cnt = 0; }
}

// ---------------------------------------------------------------------------
// k_split_all: fused split for z AND emb. fp32 -> bf16 hi + lo (residual),
// fused fp64 row sum-of-sq. Half-warp per row; block = 16 rows.
// Blocks [0, N/16) -> z ; blocks [N/16, N/16+K/16) -> emb.
// ---------------------------------------------------------------------------
__global__ __launch_bounds__(256) void k_split_all(const float* __restrict__ z,
                                                   const float* __restrict__ e) {
    const int tid  = threadIdx.x;
    const int warp = tid >> 5;
    const int lane = tid & 31;
    const int half = lane & 15;

    const float* src;
    __nv_bfloat16 *h, *l;
    float* sq;
    int rbase;
    if (blockIdx.x < NROWS / 16) {
        src = z; h = g_zh; l = g_zl; sq = g_zsq;
        rbase = blockIdx.x * 16;
    } else {
        src = e; h = g_eh; l = g_el; sq = g_esq;
        rbase = (blockIdx.x - NROWS / 16) * 16;
    }
    const int row = rbase + warp * 2 + (lane >> 4);

    const float4* srow = (const float4*)(src + (size_t)row * DDIM);
    float4 v[4];
#pragma unroll
    for (int j = 0; j < 4; j++) v[j] = srow[half * 4 + j];

    double s = 0.0;
    uint32_t hw[8], lw[8];
#pragma unroll
    for (int j = 0; j < 4; j++) {
        float4 w = v[j];
        __nv_bfloat16 h0 = __float2bfloat16_rn(w.x);
        __nv_bfloat16 h1 = __float2bfloat16_rn(w.y);
        __nv_bfloat16 h2 = __float2bfloat16_rn(w.z);
        __nv_bfloat16 h3 = __float2bfloat16_rn(w.w);
        __nv_bfloat162 hp0; hp0.x = h0; hp0.y = h1;
        __nv_bfloat162 hp1; hp1.x = h2; hp1.y = h3;
        hw[j * 2 + 0] = *(uint32_t*)&hp0;
        hw[j * 2 + 1] = *(uint32_t*)&hp1;
        __nv_bfloat162 lp0, lp1;
        lp0.x = __float2bfloat16_rn(w.x - __bfloat162float(h0));
        lp0.y = __float2bfloat16_rn(w.y - __bfloat162float(h1));
        lp1.x = __float2bfloat16_rn(w.z - __bfloat162float(h2));
        lp1.y = __float2bfloat16_rn(w.w - __bfloat162float(h3));
        lw[j * 2 + 0] = *(uint32_t*)&lp0;
        lw[j * 2 + 1] = *(uint32_t*)&lp1;
        s += (double)w.x * w.x + (double)w.y * w.y
           + (double)w.z * w.z + (double)w.w * w.w;
    }
    uint4* hp = (uint4*)(h + (size_t)row * DDIM + half * 16);
    uint4* lp = (uint4*)(l + (size_t)row * DDIM + half * 16);
    hp[0] = make_uint4(hw[0], hw[1], hw[2], hw[3]);
    hp[1] = make_uint4(hw[4], hw[5], hw[6], hw[7]);
    lp[0] = make_uint4(lw[0], lw[1], lw[2], lw[3]);
    lp[1] = make_uint4(lw[4], lw[5], lw[6], lw[7]);

#pragma unroll
    for (int off = 8; off > 0; off >>= 1)
        s += __shfl_xor_sync(0xffffffffu, s, off);
    if (half == 0) sq[row] = (float)s;
}

// ---------------------------------------------------------------------------
// async-copy / mma helpers
// ---------------------------------------------------------------------------
__device__ __forceinline__ void cp_async16(uint32_t dst, const void* src) {
    asm volatile("cp.async.cg.shared.global [%0], [%1], 16;" :: "r"(dst), "l"(src));
}
__device__ __forceinline__ void cp_commit() {
    asm volatile("cp.async.commit_group;");
}
template <int N> __device__ __forceinline__ void cp_wait() {
    asm volatile("cp.async.wait_group %0;" :: "n"(N));
}
__device__ __forceinline__ void ldsm_x4(uint32_t& r0, uint32_t& r1, uint32_t& r2, uint32_t& r3,
                                        uint32_t addr) {
    asm volatile("ldmatrix.sync.aligned.m8n8.x4.shared.b16 {%0,%1,%2,%3}, [%4];"
                 : "=r"(r0), "=r"(r1), "=r"(r2), "=r"(r3) : "r"(addr));
}
__device__ __forceinline__ void mma_bf16(float* cfr, uint32_t a0, uint32_t a1, uint32_t a2,
                                         uint32_t a3, uint32_t b0, uint32_t b1) {
    asm volatile("mma.sync.aligned.m16n8k16.row.col.f32.bf16.bf16.f32 "
                 "{%0,%1,%2,%3}, {%4,%5,%6,%7}, {%8,%9}, {%0,%1,%2,%3};"
                 : "+f"(cfr[0]), "+f"(cfr[1]), "+f"(cfr[2]), "+f"(cfr[3])
                 : "r"(a0), "r"(a1), "r"(a2), "r"(a3), "r"(b0), "r"(b1));
}
__device__ __forceinline__ void upd(float& b, float& s, int& i, float v, int col) {
    if (v < b) { s = b; b = v; i = col; }
    else if (v < s) { s = v; }
}
__device__ __forceinline__ void merge2(float& b, float& s, int& i,
                                       float ob, float os, int oi) {
    float ns = fminf(s, os);
    if (ob < b || (ob == b && oi < i)) { ns = fminf(ns, b); b = ob; i = oi; }
    else { ns = fminf(ns, ob); }
    s = ns;
}

// ---------------------------------------------------------------------------
// Kernel 1: 3-term bf16-split GEMM via mma.sync, cp.async double-buffered,
// fused quantized-distance argmin, fused flag compaction, fused loss sum.
// (byte-identical to the R12/R13 passing version)
// ---------------------------------------------------------------------------
#define PITCH_B   80
#define TILE_ST   (128 * PITCH_B)
#define STAGE_ST  (4 * TILE_ST)
#define SMEM_TILES (2 * STAGE_ST)
#define SMEM_K1   (SMEM_TILES + 512 + 3 * 1024)

__global__ __launch_bounds__(256, 2) void k1_mma(int* __restrict__ codes_i,
                                                 float* __restrict__ codes_f) {
    extern __shared__ char smem[];
    float* sEsq = (float*)(smem + SMEM_TILES);
    float* sFb  = (float*)(smem + SMEM_TILES + 512);
    float* sFs  = (float*)(smem + SMEM_TILES + 512 + 1024);
    int*   sFi  = (int*)  (smem + SMEM_TILES + 512 + 2048);

    const int tid  = threadIdx.x;
    const int lane = tid & 31;
    const int warp = tid >> 5;
    const int wm   = warp & 3;
    const int wn   = warp >> 2;
    const int row0 = blockIdx.x * 128;
    const uint32_t sbase = (uint32_t)__cvta_generic_to_shared(smem);

    const int rbase = wm * 32 + (lane >> 2);
    float zs[4];
#pragma unroll
    for (int r = 0; r < 4; r++) zs[r] = g_zsq[row0 + rbase + r * 8];

    float best[4], secv[4];
    int   bidx[4];
#pragma unroll
    for (int r = 0; r < 4; r++) { best[r] = 3.0e38f; secv[r] = 3.0e38f; bidx[r] = 0x7fffffff; }

    auto issue = [&](int kc, int st, int n0) {
        const int k0 = kc * 32;
#pragma unroll
        for (int it = 0; it < 8; it++) {
            int tile = it >> 1;
            int rr   = ((tid >> 2) + it * 64) & 127;
            int sub  = tid & 3;
            const __nv_bfloat16* gp;
            if      (tile == 0) gp = g_zh + (size_t)(row0 + rr) * DDIM;
            else if (tile == 1) gp = g_zl + (size_t)(row0 + rr) * DDIM;
            else if (tile == 2) gp = g_eh + (size_t)(n0 + rr) * DDIM;
            else                gp = g_el + (size_t)(n0 + rr) * DDIM;
            uint32_t dst = sbase + st * STAGE_ST + tile * TILE_ST + rr * PITCH_B + sub * 16;
            cp_async16(dst, gp + k0 + sub * 8);
        }
        cp_commit();
    };

    for (int n0 = 0; n0 < KCODES; n0 += 128) {
        __syncthreads();
        if (tid < 128) sEsq[tid] = g_esq[n0 + tid];

        float acc[2][8][4];
#pragma unroll
        for (int mt = 0; mt < 2; mt++)
#pragma unroll
            for (int nt = 0; nt < 8; nt++)
#pragma unroll
                for (int q = 0; q < 4; q++) acc[mt][nt][q] = 0.0f;

        issue(0, 0, n0);

        for (int kc = 0; kc < 8; kc++) {
            if (kc < 7) issue(kc + 1, (kc + 1) & 1, n0);
            if (kc < 7) cp_wait<1>(); else cp_wait<0>();
            __syncthreads();

            const int st = kc & 1;
            const uint32_t bAh = sbase + st * STAGE_ST;
            const uint32_t bAl = bAh + TILE_ST;
            const uint32_t bBh = bAh + 2 * TILE_ST;
            const uint32_t bBl = bAh + 3 * TILE_ST;

#pragma unroll
            for (int ks = 0; ks < 2; ks++) {
                const uint32_t koff = ks * 32;
                uint32_t Ah[2][4], Al[2][4];
#pragma unroll
                for (int mt = 0; mt < 2; mt++) {
                    uint32_t off = (uint32_t)(wm * 32 + mt * 16 + (lane & 15)) * PITCH_B
                                 + koff + ((lane >> 4) & 1) * 16;
                    ldsm_x4(Ah[mt][0], Ah[mt][1], Ah[mt][2], Ah[mt][3], bAh + off);
                    ldsm_x4(Al[mt][0], Al[mt][1], Al[mt][2], Al[mt][3], bAl + off);
                }
                const int g  = lane >> 3;
                const int rb = lane & 7;
#pragma unroll
                for (int ntp = 0; ntp < 4; ntp++) {
                    uint32_t nrow = (uint32_t)(wn * 64 + (ntp * 2 + (g >> 1)) * 8 + rb);
                    uint32_t off  = nrow * PITCH_B + koff + (g & 1) * 16;
                    uint32_t Bh0, Bh1, Bh2, Bh3, Bl0, Bl1, Bl2, Bl3;
                    ldsm_x4(Bh0, Bh1, Bh2, Bh3, bBh + off);
                    ldsm_x4(Bl0, Bl1, Bl2, Bl3, bBl + off);
                    const int nt0 = ntp * 2, nt1 = nt0 + 1;
#pragma unroll
                    for (int mt = 0; mt < 2; mt++) {
                        mma_bf16(acc[mt][nt0], Ah[mt][0], Ah[mt][1], Ah[mt][2], Ah[mt][3], Bh0, Bh1);
                        mma_bf16(acc[mt][nt0], Al[mt][0], Al[mt][1], Al[mt][2], Al[mt][3], Bh0, Bh1);
                        mma_bf16(acc[mt][nt0], Ah[mt][0], Ah[mt][1], Ah[mt][2], Ah[mt][3], Bl0, Bl1);
                        mma_bf16(acc[mt][nt1], Ah[mt][0], Ah[mt][1], Ah[mt][2], Ah[mt][3], Bh2, Bh3);
                        mma_bf16(acc[mt][nt1], Al[mt][0], Al[mt][1], Al[mt][2], Al[mt][3], Bh2, Bh3);
                        mma_bf16(acc[mt][nt1], Ah[mt][0], Ah[mt][1], Ah[mt][2], Ah[mt][3], Bl2, Bl3);
                    }
                }
            }
            __syncthreads();
        }

        const int qc = lane & 3;
#pragma unroll
        for (int nt = 0; nt < 8; nt++) {
#pragma unroll
            for (int cp = 0; cp < 2; cp++) {
                int cl  = wn * 64 + nt * 8 + qc * 2 + cp;
                float esq = sEsq[cl];
                int col = n0 + cl;
                float v;
                v = __fadd_rn(__fadd_rn(zs[0], -2.0f * acc[0][nt][cp]),     esq);
                upd(best[0], secv[0], bidx[0], v, col);
                v = __fadd_rn(__fadd_rn(zs[1], -2.0f * acc[0][nt][2 + cp]), esq);
                upd(best[1], secv[1], bidx[1], v, col);
                v = __fadd_rn(__fadd_rn(zs[2], -2.0f * acc[1][nt][cp]),     esq);
                upd(best[2], secv[2], bidx[2], v, col);
                v = __fadd_rn(__fadd_rn(zs[3], -2.0f * acc[1][nt][2 + cp]), esq);
                upd(best[3], secv[3], bidx[3], v, col);
            }
        }
    }

#pragma unroll
    for (int off = 1; off <= 2; off <<= 1) {
#pragma unroll
        for (int r = 0; r < 4; r++) {
            float ob = __shfl_xor_sync(0xffffffffu, best[r], off);
            float os = __shfl_xor_sync(0xffffffffu, secv[r], off);
            int   oi = __shfl_xor_sync(0xffffffffu, bidx[r], off);
            merge2(best[r], secv[r], bidx[r], ob, os, oi);
        }
    }
    if ((lane & 3) == 0) {
#pragma unroll
        for (int r = 0; r < 4; r++) {
            int rl = wm * 32 + (lane >> 2) + r * 8;
            sFb[rl * 2 + wn] = best[r];
            sFs[rl * 2 + wn] = secv[r];
            sFi[rl * 2 + wn] = bidx[r];
        }
    }
    __syncthreads();
    float* sLoss = sFs;
    if (tid < 128) {
        float b = sFb[tid * 2], s = sFs[tid * 2];
        int   i = sFi[tid * 2];
        merge2(b, s, i, sFb[tid * 2 + 1], sFs[tid * 2 + 1], sFi[tid * 2 + 1]);
        int row = row0 + tid;
        codes_i[row] = i;
        codes_f[row] = (float)i;
        if (s - b <= GAPF) {
            int p = atomicAdd(&g_flag_cnt, 1);
            g_flag_list[p] = row;
        }
        sFb[tid] = b;
    }
    __syncthreads();
    if (tid < 64) sLoss[tid] = sFb[tid] + sFb[tid + 64];
    __syncthreads();
    if (tid < 32) {
        float s = sLoss[tid] + sLoss[tid + 32];
#pragma unroll
        for (int off = 16; off > 0; off >>= 1)
            s += __shfl_down_sync(0xffffffffu, s, off);
        if (tid == 0) atomicAdd(&g_loss, (double)s);
    }
}

// ---------------------------------------------------------------------------
// k1_refine: exact fp64-dot recompute for flagged rows.
// (byte-identical to the R13 passing version)
// ---------------------------------------------------------------------------
__global__ __launch_bounds__(256) void k1_refine(const float* __restrict__ z,
                                                 const float* __restrict__ emb,
                                                 int* __restrict__ codes_i,
                                                 float* __restrict__ codes_f) {
    __shared__ float zrow[DDIM];
    __shared__ float sv[256];
    __shared__ int   si[256];
    int t = threadIdx.x;
    int cnt = g_flag_cnt;
    for (int fi = blockIdx.x; fi < cnt; fi += gridDim.x) {
        int row = g_flag_list[fi];
        zrow[t] = z[(size_t)row * DDIM + t];
        __syncthreads();

        float zsq = g_zsq[row];
        float bv = 3.0e38f;
        int   bi = 0x7fffffff;
        for (int c = t; c < KCODES; c += 256) {
            const float4* e4 = (const float4*)(emb + (size_t)c * DDIM);
            const float4* z4 = (const float4*)zrow;
            double dot = 0.0;
#pragma unroll 8
            for (int q = 0; q < DDIM / 4; q++) {
                float4 ev = e4[q];
                float4 zv = z4[q];
                dot += (double)zv.x * ev.x + (double)zv.y * ev.y
                     + (double)zv.z * ev.z + (double)zv.w * ev.w;
            }
            float m = (float)(2.0 * dot);
            float u = __fadd_rn(zsq, -m);
            float v = __fadd_rn(u, g_esq[c]);
            if (v < bv) { bv = v; bi = c; }
        }
        sv[t] = bv; si[t] = bi;
        __syncthreads();
        for (int s = 128; s > 0; s >>= 1) {
            if (t < s) {
                float v = sv[t + s]; int id = si[t + s];
                if (v < sv[t] || (v == sv[t] && id < si[t])) { sv[t] = v; si[t] = id; }
            }
            __syncthreads();
        }
        if (t == 0) {
            codes_i[row] = si[0];
            codes_f[row] = (float)si[0];
        }
        __syncthreads();
    }
}

// ---------------------------------------------------------------------------
// kH: histogram of final codes (smem-aggregated). grid 64 x 256, 4 rows/thr.
// ---------------------------------------------------------------------------
__global__ __launch_bounds__(256) void kH() {
    __shared__ int sh[KCODES];
    int t = threadIdx.x;
    for (int i = t; i < KCODES; i += 256) sh[i] = 0;
    __syncthreads();
    int base = blockIdx.x * 1024;
#pragma unroll
    for (int i = 0; i < 4; i++)
        atomicAdd(&sh[g_codes[base + t + i * 256]], 1);
    __syncthreads();
    for (int i = t; i < KCODES; i += 256)
        if (sh[i]) atomicAdd(&g_hist[i], sh[i]);
}

// ---------------------------------------------------------------------------
// kP: prefix-scan of hist + new_cluster_size + nsum + vq_loss. One block.
// ---------------------------------------------------------------------------
__global__ __launch_bounds__(KCODES) void kP(const float* __restrict__ cs_in,
                                             float* __restrict__ cs_out,
                                             float* __restrict__ loss_out,
                                             float inv_nd) {
    __shared__ int sc[KCODES], sc2[KCODES];
    __shared__ float red[KCODES];
    int t = threadIdx.x;
    int hcnt = g_hist[t];
    sc[t] = hcnt;
    __syncthreads();
    int* src = sc;
    int* dst = sc2;
    for (int off = 1; off < KCODES; off <<= 1) {
        int v = src[t];
        if (t >= off) v += src[t - off];
        dst[t] = v;
        __syncthreads();
        int* tmp = src; src = dst; dst = tmp;
    }
    int excl = src[t] - hcnt;
    g_off[t] = excl;
    g_cursor[t] = excl;
    float ncs = cs_in[t] * DECAYF + (float)hcnt * ONE_MINUS_DECAY;
    cs_out[t] = ncs;
    red[t] = ncs;
    __syncthreads();
    for (int s = KCODES / 2; s > 0; s >>= 1) {
        if (t < s) red[t] += red[t + s];
        __syncthreads();
    }
    if (t == 0) {
        g_nsum = red[0];
        loss_out[0] = BETAF * (float)(g_loss * (double)inv_nd);
    }
}

// ---------------------------------------------------------------------------
// kS: scatter row ids by code (cursor atomics). grid 256 x 256.
// ---------------------------------------------------------------------------
__global__ __launch_bounds__(256) void kS() {
    int row = blockIdx.x * 256 + threadIdx.x;
    int c = g_codes[row];
    int p = atomicAdd(&g_cursor[c], 1);
    g_row_of[p] = row;
}

// ---------------------------------------------------------------------------
// kSum: segmented sum -> embed_sum AND zq write (fused gather).
// One block per code; thread t owns dim t; emb[c][t] held in a register.
// ---------------------------------------------------------------------------
__global__ __launch_bounds__(DDIM) void kSum(const float* __restrict__ z,
                                             const float* __restrict__ emb,
                                             float* __restrict__ zq_out) {
    int c = blockIdx.x;
    int t = threadIdx.x;
    int off = g_off[c];
    int cnt = g_hist[c];
    float ev = emb[(size_t)c * DDIM + t];
    float acc = 0.0f;
    int i = 0;
    for (; i + 4 <= cnt; i += 4) {
        int r0 = g_row_of[off + i];
        int r1 = g_row_of[off + i + 1];
        int r2 = g_row_of[off + i + 2];
        int r3 = g_row_of[off + i + 3];
        acc += z[(size_t)r0 * DDIM + t] + z[(size_t)r1 * DDIM + t]
             + z[(size_t)r2 * DDIM + t] + z[(size_t)r3 * DDIM + t];
        zq_out[(size_t)r0 * DDIM + t] = ev;
        zq_out[(size_t)r1 * DDIM + t] = ev;
        zq_out[(size_t)r2 * DDIM + t] = ev;
        zq_out[(size_t)r3 * DDIM + t] = ev;
    }
    for (; i < cnt; i++) {
        int r = g_row_of[off + i];
        acc += z[(size_t)r * DDIM + t];
        zq_out[(size_t)r * DDIM + t] = ev;
    }
    g_embed_sum[(size_t)c * DDIM + t] = acc;
}

// ---------------------------------------------------------------------------
// k4: new_embed_avg + smoothed normalize -> new_embedding
// ---------------------------------------------------------------------------
__global__ __launch_bounds__(DDIM) void k4_embed(const float* __restrict__ avg_in,
                                                 const float* __restrict__ cs_out,
                                                 float* __restrict__ avg_out,
                                                 float* __restrict__ emb_out) {
    int k = blockIdx.x;
    int t = threadIdx.x;
    size_t idx = (size_t)k * DDIM + t;
    float na = avg_in[idx] * DECAYF + g_embed_sum[idx] * ONE_MINUS_DECAY;
    avg_out[idx] = na;
    float n = g_nsum;
    float css = (cs_out[k] + EPSF) / (n + (float)KCODES * EPSF) * n;
    emb_out[idx] = na / css;
}

// ---------------------------------------------------------------------------
extern "C" void kernel_launch(void* const* d_in, const int* in_sizes, int n_in,
                              void* d_out, int out_size) {
    const float* z_e  = (const float*)d_in[0];  // [N, D]
    const float* emb  = (const float*)d_in[1];  // [K, D]
    const float* cs   = (const float*)d_in[2];  // [K]
    const float* eavg = (const float*)d_in[3];  // [K, D]

    const int n_ze = in_sizes[0];               // N*D
    const int KD   = in_sizes[1];               // K*D
    const int Kk   = in_sizes[2];               // K
    const int D    = KD / Kk;
    const int N    = n_ze / D;

    float* out = (float*)d_out;
    // Tuple order: z_q_st, vq_loss, codes, new_embedding, new_cluster_size, new_embed_avg
    float* o_zq    = out;
    float* o_loss  = out + (size_t)n_ze;
    float* o_codes = o_loss + 1;
    float* o_emb   = o_codes + N;
    float* o_cs    = o_emb + KD;
    float* o_avg   = o_cs + Kk;

    int* codes_dev;
    cudaGetSymbolAddress((void**)&codes_dev, g_codes);

    cudaFuncSetAttribute(k1_mma, cudaFuncAttributeMaxDynamicSharedMemorySize, SMEM_K1);

    k_init_small<<<1, 1024>>>();
    k_split_all<<<N / 16 + Kk / 16, 256>>>(z_e, emb);
    k1_mma<<<N / 128, 256, SMEM_K1>>>(codes_dev, o_codes);
    k1_refine<<<256, 256>>>(z_e, emb, codes_dev, o_codes);
    kH<<<N / 1024, 256>>>();
    kP<<<1, Kk>>>(cs, o_cs, o_loss, 1.0f / (float)n_ze);
    kS<<<N / 256, 256>>>();
    kSum<<<Kk, D>>>(z_e, emb, o_zq);
    k4_embed<<<Kk, D>>>(eavg, o_cs, o_avg, o_emb);
}